// round 1
// baseline (speedup 1.0000x reference)
#include <cuda_runtime.h>
#include <math.h>

#define BATCH 2
#define SEQ   2048
#define EMB   1024
#define HEADS 16
#define HDIM  64
#define NROWS (BATCH*SEQ)

// Scratch (allocation-free rule: __device__ globals)
__device__ float g_q[NROWS*EMB];
__device__ float g_k[NROWS*EMB];
__device__ float g_v[NROWS*EMB];
__device__ float g_ctx[NROWS*EMB];

// ---------------------------------------------------------------------------
// GEMM NT: C[n][j] = sum_e A[n][e] * W[j][e];  A: [NROWS x EMB], W: [EMB x EMB]
// 64x64 tile, 256 threads, 4x4 micro-tile, k-step 16.
// ---------------------------------------------------------------------------
__global__ __launch_bounds__(256) void gemm_nt(const float* __restrict__ A,
                                               const float* __restrict__ W,
                                               float* __restrict__ C) {
    __shared__ float As[64][17];
    __shared__ float Ws[64][17];
    const int tid = threadIdx.x;
    const int tx = tid & 15, ty = tid >> 4;
    const int j0 = blockIdx.x * 64, n0 = blockIdx.y * 64;
    const int lr = tid >> 2, lc = (tid & 3) * 4;

    const float* Ag = A + (size_t)(n0 + lr) * EMB + lc;
    const float* Wg = W + (size_t)(j0 + lr) * EMB + lc;

    float acc[4][4] = {};

    for (int e0 = 0; e0 < EMB; e0 += 16) {
        float4 av = *(const float4*)(Ag + e0);
        float4 wv = *(const float4*)(Wg + e0);
        As[lr][lc+0] = av.x; As[lr][lc+1] = av.y; As[lr][lc+2] = av.z; As[lr][lc+3] = av.w;
        Ws[lr][lc+0] = wv.x; Ws[lr][lc+1] = wv.y; Ws[lr][lc+2] = wv.z; Ws[lr][lc+3] = wv.w;
        __syncthreads();
        #pragma unroll
        for (int kk = 0; kk < 16; kk++) {
            float a0 = As[ty*4+0][kk], a1 = As[ty*4+1][kk],
                  a2 = As[ty*4+2][kk], a3 = As[ty*4+3][kk];
            float b0 = Ws[tx*4+0][kk], b1 = Ws[tx*4+1][kk],
                  b2 = Ws[tx*4+2][kk], b3 = Ws[tx*4+3][kk];
            acc[0][0] += a0*b0; acc[0][1] += a0*b1; acc[0][2] += a0*b2; acc[0][3] += a0*b3;
            acc[1][0] += a1*b0; acc[1][1] += a1*b1; acc[1][2] += a1*b2; acc[1][3] += a1*b3;
            acc[2][0] += a2*b0; acc[2][1] += a2*b1; acc[2][2] += a2*b2; acc[2][3] += a2*b3;
            acc[3][0] += a3*b0; acc[3][1] += a3*b1; acc[3][2] += a3*b2; acc[3][3] += a3*b3;
        }
        __syncthreads();
    }

    #pragma unroll
    for (int i = 0; i < 4; i++) {
        float4 v = make_float4(acc[i][0], acc[i][1], acc[i][2], acc[i][3]);
        *(float4*)&C[(size_t)(n0 + ty*4 + i) * EMB + j0 + tx*4] = v;
    }
}

// ---------------------------------------------------------------------------
// RoPE applied in-place to q and k. One thread per (b,s,h,d<32) pair.
// ---------------------------------------------------------------------------
__global__ __launch_bounds__(256) void rope_kernel(float* __restrict__ q,
                                                   float* __restrict__ k) {
    int i = blockIdx.x * blockDim.x + threadIdx.x;   // 0 .. B*S*H*32-1
    int d = i & 31;
    int h = (i >> 5) & (HEADS - 1);
    int s = (i >> 9) & (SEQ - 1);
    int b = i >> 20;  // 9 + 11 bits

    size_t base = ((size_t)(b * SEQ + s)) * EMB + h * HDIM + d;

    // inv_freq = 10000^{-(2d)/64} = 2^{-(2d/64)*log2(10000)}
    float inv = exp2f(-(float)(2 * d) * (13.287712379549449f / 64.0f));
    float ang = (float)s * inv;
    float sn, cs;
    sincosf(ang, &sn, &cs);

    float x1 = q[base], x2 = q[base + 32];
    q[base]      = x1 * cs - x2 * sn;
    q[base + 32] = x2 * cs + x1 * sn;

    float y1 = k[base], y2 = k[base + 32];
    k[base]      = y1 * cs - y2 * sn;
    k[base + 32] = y2 * cs + y1 * sn;
}

// ---------------------------------------------------------------------------
// Causal flash attention. Block: 128 query rows (thread-per-row), key tiles of 64.
// Dynamic smem: Ks[64*64] | Vs[64*64] | Sc[128*65]
// ---------------------------------------------------------------------------
#define ATTN_SMEM ((4096 + 4096 + 128*65) * 4)

__global__ __launch_bounds__(128) void attn_kernel(const float* __restrict__ q,
                                                   const float* __restrict__ k,
                                                   const float* __restrict__ v,
                                                   float* __restrict__ ctx) {
    extern __shared__ float sm[];
    float* Ks = sm;             // 64 x 64
    float* Vs = sm + 4096;      // 64 x 64
    float* Sc = sm + 8192;      // 128 x 65 (padded)

    const int tid = threadIdx.x;
    const int qt  = blockIdx.x;          // query tile (128 rows)
    const int h   = blockIdx.y;
    const int b   = blockIdx.z;

    const size_t bh_off = (size_t)b * SEQ * EMB + h * HDIM;
    const float* kbase = k + bh_off;
    const float* vbase = v + bh_off;

    const int qi = qt * 128 + tid;       // this thread's global query row

    // load q row (pre-scaled by 1/sqrt(D))
    float qreg[64];
    {
        const float* qrow = q + bh_off + (size_t)qi * EMB;
        #pragma unroll
        for (int i = 0; i < 16; i++) {
            float4 t = *(const float4*)(qrow + i * 4);
            qreg[i*4+0] = t.x * 0.125f; qreg[i*4+1] = t.y * 0.125f;
            qreg[i*4+2] = t.z * 0.125f; qreg[i*4+3] = t.w * 0.125f;
        }
    }

    float acc[64];
    #pragma unroll
    for (int d = 0; d < 64; d++) acc[d] = 0.0f;
    float m = -1e30f, l = 0.0f;

    const int ntiles = 2 * qt + 2;       // key tiles covering causal range
    for (int kt = 0; kt < ntiles; kt++) {
        // cooperative load of K and V tiles (64x64 each) as float4
        for (int t = tid; t < 2048; t += 128) {
            int which = t >> 10;
            int idx = t & 1023;
            int row = idx >> 4;
            int c = (idx & 15) << 2;
            const float* src = (which ? vbase : kbase) + (size_t)(kt*64 + row) * EMB + c;
            float4 val = *(const float4*)src;
            float* dst = (which ? Vs : Ks) + row * 64 + c;
            *(float4*)dst = val;
        }
        __syncthreads();

        const bool need_mask = (kt * 64 + 63) > qi;

        // Phase 1: scores for this row
        float tm = -1e30f;
        for (int j = 0; j < 64; j++) {
            const float4* K4 = (const float4*)(Ks + j * 64);
            float s = 0.0f;
            #pragma unroll
            for (int i = 0; i < 16; i++) {
                float4 kv = K4[i];
                s += qreg[i*4+0]*kv.x + qreg[i*4+1]*kv.y
                   + qreg[i*4+2]*kv.z + qreg[i*4+3]*kv.w;
            }
            if (need_mask && (kt*64 + j) > qi) s = -1e30f;
            Sc[tid*65 + j] = s;
            tm = fmaxf(tm, s);
        }

        // online softmax rescale
        float mnew = fmaxf(m, tm);
        float alpha = __expf(m - mnew);
        l *= alpha;
        #pragma unroll
        for (int d = 0; d < 64; d++) acc[d] *= alpha;
        m = mnew;

        // Phase 2: P*V
        for (int j = 0; j < 64; j++) {
            float p = __expf(Sc[tid*65 + j] - m);
            l += p;
            const float4* V4 = (const float4*)(Vs + j * 64);
            #pragma unroll
            for (int i = 0; i < 16; i++) {
                float4 vv = V4[i];
                acc[i*4+0] += p * vv.x; acc[i*4+1] += p * vv.y;
                acc[i*4+2] += p * vv.z; acc[i*4+3] += p * vv.w;
            }
        }
        __syncthreads();
    }

    // write context row
    float inv_l = 1.0f / l;
    float* orow = ctx + bh_off + (size_t)qi * EMB;
    #pragma unroll
    for (int i = 0; i < 16; i++) {
        float4 t = make_float4(acc[i*4+0]*inv_l, acc[i*4+1]*inv_l,
                               acc[i*4+2]*inv_l, acc[i*4+3]*inv_l);
        *(float4*)(orow + i * 4) = t;
    }
}

// ---------------------------------------------------------------------------
extern "C" void kernel_launch(void* const* d_in, const int* in_sizes, int n_in,
                              void* d_out, int out_size) {
    const float* x  = (const float*)d_in[0];
    const float* Wq = (const float*)d_in[1];
    const float* Wk = (const float*)d_in[2];
    const float* Wv = (const float*)d_in[3];
    const float* Wo = (const float*)d_in[4];
    float* out = (float*)d_out;

    float *qp, *kp, *vp, *cp;
    cudaGetSymbolAddress((void**)&qp, g_q);
    cudaGetSymbolAddress((void**)&kp, g_k);
    cudaGetSymbolAddress((void**)&vp, g_v);
    cudaGetSymbolAddress((void**)&cp, g_ctx);

    cudaFuncSetAttribute(attn_kernel, cudaFuncAttributeMaxDynamicSharedMemorySize, ATTN_SMEM);

    dim3 ggrid(EMB / 64, NROWS / 64);

    gemm_nt<<<ggrid, 256>>>(x, Wq, qp);
    gemm_nt<<<ggrid, 256>>>(x, Wk, kp);
    gemm_nt<<<ggrid, 256>>>(x, Wv, vp);

    rope_kernel<<<(BATCH * SEQ * HEADS * 32) / 256, 256>>>(qp, kp);

    attn_kernel<<<dim3(SEQ / 128, HEADS, BATCH), 128, ATTN_SMEM>>>(qp, kp, vp, cp);

    gemm_nt<<<ggrid, 256>>>(cp, Wo, out);
}

// round 7
// speedup vs baseline: 3.9798x; 3.9798x over previous
#include <cuda_runtime.h>
#include <cuda_bf16.h>
#include <cstdint>
#include <math.h>

#define BATCH 2
#define SEQ   2048
#define EMB   1024
#define HEADS 16
#define HDIM  64
#define NROWS (BATCH*SEQ)

// ---------------- scratch (__device__ globals; no allocs allowed) -----------
__device__ float g_q[NROWS*EMB];
__device__ float g_k[NROWS*EMB];
__device__ float g_v[NROWS*EMB];
__device__ float g_ctx[NROWS*EMB];
__device__ __nv_bfloat16 g_xh[NROWS*EMB], g_xl[NROWS*EMB];
__device__ __nv_bfloat16 g_ch[NROWS*EMB], g_cl[NROWS*EMB];
__device__ __nv_bfloat16 g_wh[4][EMB*EMB], g_wl[4][EMB*EMB];
__device__ __nv_bfloat16 g_qh[NROWS*EMB], g_ql[NROWS*EMB];
__device__ __nv_bfloat16 g_kh[NROWS*EMB], g_kl[NROWS*EMB];
__device__ __nv_bfloat16 g_vh[NROWS*EMB], g_vl[NROWS*EMB];

// ---------------- mma.sync helper (sm_80-level PTX, safe on sm_103) ---------
__device__ __forceinline__ void mma16816(float* c, const uint32_t* a,
                                         uint32_t b0, uint32_t b1) {
    asm volatile(
        "mma.sync.aligned.m16n8k16.row.col.f32.bf16.bf16.f32 "
        "{%0,%1,%2,%3}, {%4,%5,%6,%7}, {%8,%9}, {%0,%1,%2,%3};"
        : "+f"(c[0]), "+f"(c[1]), "+f"(c[2]), "+f"(c[3])
        : "r"(a[0]), "r"(a[1]), "r"(a[2]), "r"(a[3]), "r"(b0), "r"(b1));
}

__device__ __forceinline__ uint32_t packbf(float lo, float hi) {
    __nv_bfloat162 t = __floats2bfloat162_rn(lo, hi);   // .x = lo (low 16 bits)
    return *reinterpret_cast<uint32_t*>(&t);
}

// ---------------------------------------------------------------------------
// split fp32 -> bf16 hi + bf16 lo residual
// ---------------------------------------------------------------------------
__global__ __launch_bounds__(256) void split_kernel(const float4* __restrict__ in,
                                                    __nv_bfloat162* __restrict__ hi,
                                                    __nv_bfloat162* __restrict__ lo,
                                                    int n4) {
    int i = blockIdx.x * blockDim.x + threadIdx.x;
    if (i >= n4) return;
    float4 a = in[i];
    __nv_bfloat16 h0 = __float2bfloat16_rn(a.x);
    __nv_bfloat16 h1 = __float2bfloat16_rn(a.y);
    __nv_bfloat16 h2 = __float2bfloat16_rn(a.z);
    __nv_bfloat16 h3 = __float2bfloat16_rn(a.w);
    hi[i*2+0] = __nv_bfloat162(h0, h1);
    hi[i*2+1] = __nv_bfloat162(h2, h3);
    lo[i*2+0] = __nv_bfloat162(__float2bfloat16_rn(a.x - __bfloat162float(h0)),
                               __float2bfloat16_rn(a.y - __bfloat162float(h1)));
    lo[i*2+1] = __nv_bfloat162(__float2bfloat16_rn(a.z - __bfloat162float(h2)),
                               __float2bfloat16_rn(a.w - __bfloat162float(h3)));
}

// ---------------------------------------------------------------------------
// GEMM NT via mma.sync: C[m][n] = sum_k A[m][k]*B[n][k], bf16 split 3-pass.
// CTA tile 128x128, 8 warps (4m x 2n), warp tile 32x64. k-chunk 64 in smem.
// ---------------------------------------------------------------------------
#define GP   72           // smem pitch (bf16)
#define GPB  144          // pitch bytes
#define GT_TILE (128*GP*2)
#define GT_SMEM (4*GT_TILE)

__global__ __launch_bounds__(256) void gemm_tc(const __nv_bfloat16* __restrict__ Ah,
                                               const __nv_bfloat16* __restrict__ Al,
                                               const __nv_bfloat16* __restrict__ Bh,
                                               const __nv_bfloat16* __restrict__ Bl,
                                               float* __restrict__ C) {
    extern __shared__ char sm[];
    char* SAH = sm;
    char* SAL = sm + GT_TILE;
    char* SBH = sm + 2*GT_TILE;
    char* SBL = sm + 3*GT_TILE;

    const int tid = threadIdx.x;
    const int w = tid >> 5, lane = tid & 31, g = lane >> 2, t4 = lane & 3;
    const int wm = w & 3, wn = w >> 2;
    const int n0 = blockIdx.x * 128, m0 = blockIdx.y * 128;

    const char* gA_h = (const char*)(Ah + (size_t)m0 * EMB);
    const char* gA_l = (const char*)(Al + (size_t)m0 * EMB);
    const char* gB_h = (const char*)(Bh + (size_t)n0 * EMB);
    const char* gB_l = (const char*)(Bl + (size_t)n0 * EMB);

    float acc[2][8][4] = {};

    for (int kc = 0; kc < 16; kc++) {
        // cooperative load: 4 tiles of 128 rows x 128 bytes
        const char* gsrc[4] = { gA_h + kc*128, gA_l + kc*128, gB_h + kc*128, gB_l + kc*128 };
        char* dsts[4] = { SAH, SAL, SBH, SBL };
        #pragma unroll
        for (int mX = 0; mX < 4; mX++) {
            #pragma unroll
            for (int j = 0; j < 4; j++) {
                int idx = tid + j * 256;            // 0..1023
                int r = idx >> 3, c = idx & 7;
                uint4 v = *(const uint4*)(gsrc[mX] + (size_t)r * (EMB*2) + c*16);
                *(uint4*)(dsts[mX] + r*GPB + c*16) = v;
            }
        }
        __syncthreads();

        #pragma unroll
        for (int ks = 0; ks < 4; ks++) {
            uint32_t ah[2][4], al[2][4];
            #pragma unroll
            for (int mt = 0; mt < 2; mt++) {
                int row = wm*32 + mt*16 + g;
                const char* p = SAH + row*GPB + ks*32 + t4*4;
                ah[mt][0] = *(const uint32_t*)p;
                ah[mt][1] = *(const uint32_t*)(p + 8*GPB);
                ah[mt][2] = *(const uint32_t*)(p + 16);
                ah[mt][3] = *(const uint32_t*)(p + 8*GPB + 16);
                const char* q = SAL + row*GPB + ks*32 + t4*4;
                al[mt][0] = *(const uint32_t*)q;
                al[mt][1] = *(const uint32_t*)(q + 8*GPB);
                al[mt][2] = *(const uint32_t*)(q + 16);
                al[mt][3] = *(const uint32_t*)(q + 8*GPB + 16);
            }
            #pragma unroll
            for (int nt = 0; nt < 8; nt++) {
                int brow = wn*64 + nt*8 + g;
                const char* p = SBH + brow*GPB + ks*32 + t4*4;
                uint32_t bh0 = *(const uint32_t*)p;
                uint32_t bh1 = *(const uint32_t*)(p + 16);
                const char* q = SBL + brow*GPB + ks*32 + t4*4;
                uint32_t bl0 = *(const uint32_t*)q;
                uint32_t bl1 = *(const uint32_t*)(q + 16);
                mma16816(acc[0][nt], ah[0], bh0, bh1);
                mma16816(acc[1][nt], ah[1], bh0, bh1);
                mma16816(acc[0][nt], al[0], bh0, bh1);
                mma16816(acc[1][nt], al[1], bh0, bh1);
                mma16816(acc[0][nt], ah[0], bl0, bl1);
                mma16816(acc[1][nt], ah[1], bl0, bl1);
            }
        }
        __syncthreads();
    }

    #pragma unroll
    for (int mt = 0; mt < 2; mt++) {
        int row = m0 + wm*32 + mt*16 + g;
        #pragma unroll
        for (int nt = 0; nt < 8; nt++) {
            float* p0 = C + (size_t)row * EMB + n0 + wn*64 + nt*8 + t4*2;
            *(float2*)p0 = make_float2(acc[mt][nt][0], acc[mt][nt][1]);
            *(float2*)(p0 + 8*EMB) = make_float2(acc[mt][nt][2], acc[mt][nt][3]);
        }
    }
}

// ---------------------------------------------------------------------------
// RoPE + bf16 split for q,k (reads fp32 q,k; writes hi/lo bf16)
// ---------------------------------------------------------------------------
__global__ __launch_bounds__(256) void rope_split(const float* __restrict__ q,
                                                  const float* __restrict__ k,
                                                  __nv_bfloat16* __restrict__ qh,
                                                  __nv_bfloat16* __restrict__ ql,
                                                  __nv_bfloat16* __restrict__ kh,
                                                  __nv_bfloat16* __restrict__ kl) {
    int i = blockIdx.x * blockDim.x + threadIdx.x;
    int d = i & 31;
    int h = (i >> 5) & (HEADS - 1);
    int s = (i >> 9) & (SEQ - 1);
    int b = i >> 20;

    size_t base = ((size_t)(b * SEQ + s)) * EMB + h * HDIM + d;
    float inv = exp2f(-(float)(2 * d) * (13.287712379549449f / 64.0f));
    float ang = (float)s * inv;
    float sn, cs;
    sincosf(ang, &sn, &cs);

    float x1 = q[base], x2 = q[base + 32];
    float o1 = x1 * cs - x2 * sn;
    float o2 = x2 * cs + x1 * sn;
    __nv_bfloat16 h1 = __float2bfloat16_rn(o1), h2 = __float2bfloat16_rn(o2);
    qh[base] = h1;      ql[base]      = __float2bfloat16_rn(o1 - __bfloat162float(h1));
    qh[base + 32] = h2; ql[base + 32] = __float2bfloat16_rn(o2 - __bfloat162float(h2));

    float y1 = k[base], y2 = k[base + 32];
    float p1 = y1 * cs - y2 * sn;
    float p2 = y2 * cs + y1 * sn;
    __nv_bfloat16 j1 = __float2bfloat16_rn(p1), j2 = __float2bfloat16_rn(p2);
    kh[base] = j1;      kl[base]      = __float2bfloat16_rn(p1 - __bfloat162float(j1));
    kh[base + 32] = j2; kl[base + 32] = __float2bfloat16_rn(p2 - __bfloat162float(j2));
}

// ---------------------------------------------------------------------------
// mma.sync flash attention (causal). CTA: 128 q-rows x (b,h). 8 warps x 16 rows.
// Key tiles of 64. smem: KH,KL [64][72] bf16 ; VTH,VTL transposed [64 d][72 keys].
// ---------------------------------------------------------------------------
#define AT_TILE (64*GP*2)          // 9216 B
#define ATTN_SMEM (4*AT_TILE)      // 36864 B

__global__ __launch_bounds__(256) void attn_mma(const __nv_bfloat16* __restrict__ qh,
                                                const __nv_bfloat16* __restrict__ ql,
                                                const __nv_bfloat16* __restrict__ kh,
                                                const __nv_bfloat16* __restrict__ kl,
                                                const __nv_bfloat16* __restrict__ vh,
                                                const __nv_bfloat16* __restrict__ vl,
                                                float* __restrict__ ctx) {
    extern __shared__ char sm[];
    char* KH = sm;
    char* KL = sm + AT_TILE;
    __nv_bfloat16* VTH = (__nv_bfloat16*)(sm + 2*AT_TILE);
    __nv_bfloat16* VTL = (__nv_bfloat16*)(sm + 3*AT_TILE);

    const int tid = threadIdx.x;
    const int w = tid >> 5, lane = tid & 31, g = lane >> 2, t4 = lane & 3;
    const int qt = blockIdx.x, h = blockIdx.y, b = blockIdx.z;

    const int row_base = qt*128 + w*16;
    const int row0 = row_base + g;
    const int row1 = row0 + 8;
    const size_t hoff = (size_t)h * HDIM;

    // Q fragments (hi/lo), k-dim = HDIM handled as 4 chunks of 16
    uint32_t aqh[4][4], aql[4][4];
    {
        size_t qb = ((size_t)(b*SEQ) + row0) * EMB + hoff;
        #pragma unroll
        for (int ks = 0; ks < 4; ks++) {
            const __nv_bfloat16* p = qh + qb + ks*16 + t4*2;
            aqh[ks][0] = *(const uint32_t*)p;
            aqh[ks][1] = *(const uint32_t*)(p + 8*EMB);
            aqh[ks][2] = *(const uint32_t*)(p + 8);
            aqh[ks][3] = *(const uint32_t*)(p + 8*EMB + 8);
            const __nv_bfloat16* q2 = ql + qb + ks*16 + t4*2;
            aql[ks][0] = *(const uint32_t*)q2;
            aql[ks][1] = *(const uint32_t*)(q2 + 8*EMB);
            aql[ks][2] = *(const uint32_t*)(q2 + 8);
            aql[ks][3] = *(const uint32_t*)(q2 + 8*EMB + 8);
        }
    }

    float accO[8][4] = {};
    float m0 = -1e30f, m1 = -1e30f, l0 = 0.0f, l1 = 0.0f;
    const float Cs = 0.125f * 1.4426950408889634f;   // scale * log2(e)

    const int ntiles = 2*qt + 2;
    for (int kt = 0; kt < ntiles; kt++) {
        // ---- cooperative loads ----
        const size_t kvb = ((size_t)(b*SEQ) + kt*64) * EMB + hoff;
        #pragma unroll
        for (int j = 0; j < 2; j++) {
            int idx = tid + j*256;           // 0..511
            int r = idx >> 3, c = idx & 7;
            *(uint4*)(KH + r*GPB + c*16) = *(const uint4*)((const char*)(kh + kvb + (size_t)r*EMB) + c*16);
            *(uint4*)(KL + r*GPB + c*16) = *(const uint4*)((const char*)(kl + kvb + (size_t)r*EMB) + c*16);
        }
        {   // V transpose: thread -> (key = tid/4, d-block = (tid%4)*16)
            int key = tid >> 2;
            int db  = (tid & 3) * 16;
            const __nv_bfloat16* sh = vh + kvb + (size_t)key*EMB + db;
            const __nv_bfloat16* sl = vl + kvb + (size_t)key*EMB + db;
            uint4 u0 = *(const uint4*)sh, u1 = *(const uint4*)(sh + 8);
            uint4 w0 = *(const uint4*)sl, w1 = *(const uint4*)(sl + 8);
            const __nv_bfloat16* e0 = (const __nv_bfloat16*)&u0;
            const __nv_bfloat16* e1 = (const __nv_bfloat16*)&u1;
            const __nv_bfloat16* f0 = (const __nv_bfloat16*)&w0;
            const __nv_bfloat16* f1 = (const __nv_bfloat16*)&w1;
            #pragma unroll
            for (int i = 0; i < 8; i++) {
                VTH[(db+i)*GP + key]   = e0[i];
                VTH[(db+8+i)*GP + key] = e1[i];
                VTL[(db+i)*GP + key]   = f0[i];
                VTL[(db+8+i)*GP + key] = f1[i];
            }
        }
        __syncthreads();

        if (kt*64 <= row_base + 15) {     // tile not fully masked for this warp
            // ---- S = Q K^T (3-pass split) ----
            float s[8][4] = {};
            #pragma unroll
            for (int ks = 0; ks < 4; ks++) {
                #pragma unroll
                for (int nt = 0; nt < 8; nt++) {
                    const char* p = KH + (nt*8+g)*GPB + ks*32 + t4*4;
                    uint32_t bh0 = *(const uint32_t*)p;
                    uint32_t bh1 = *(const uint32_t*)(p + 16);
                    const char* q2 = KL + (nt*8+g)*GPB + ks*32 + t4*4;
                    uint32_t bl0 = *(const uint32_t*)q2;
                    uint32_t bl1 = *(const uint32_t*)(q2 + 16);
                    mma16816(s[nt], aqh[ks], bh0, bh1);
                    mma16816(s[nt], aql[ks], bh0, bh1);
                    mma16816(s[nt], aqh[ks], bl0, bl1);
                }
            }
            // ---- mask + scale ----
            #pragma unroll
            for (int nt = 0; nt < 8; nt++) {
                int colb = kt*64 + nt*8 + t4*2;
                s[nt][0] = (colb     > row0) ? -3e28f : s[nt][0]*Cs;
                s[nt][1] = (colb + 1 > row0) ? -3e28f : s[nt][1]*Cs;
                s[nt][2] = (colb     > row1) ? -3e28f : s[nt][2]*Cs;
                s[nt][3] = (colb + 1 > row1) ? -3e28f : s[nt][3]*Cs;
            }
            // ---- row max (quad reduce) ----
            float rm0 = -3e28f, rm1 = -3e28f;
            #pragma unroll
            for (int nt = 0; nt < 8; nt++) {
                rm0 = fmaxf(rm0, fmaxf(s[nt][0], s[nt][1]));
                rm1 = fmaxf(rm1, fmaxf(s[nt][2], s[nt][3]));
            }
            rm0 = fmaxf(rm0, __shfl_xor_sync(0xffffffffu, rm0, 1));
            rm0 = fmaxf(rm0, __shfl_xor_sync(0xffffffffu, rm0, 2));
            rm1 = fmaxf(rm1, __shfl_xor_sync(0xffffffffu, rm1, 1));
            rm1 = fmaxf(rm1, __shfl_xor_sync(0xffffffffu, rm1, 2));

            float mn0 = fmaxf(m0, rm0), mn1 = fmaxf(m1, rm1);
            float alpha0 = exp2f(m0 - mn0), alpha1 = exp2f(m1 - mn1);
            m0 = mn0; m1 = mn1;

            // ---- p = exp2(s - m), pack to bf16 hi/lo A-fragments ----
            float sum0 = 0.0f, sum1 = 0.0f;
            uint32_t aph[4][4], apl[4][4];
            #pragma unroll
            for (int nt = 0; nt < 8; nt++) {
                float p0 = exp2f(s[nt][0] - m0);
                float p1 = exp2f(s[nt][1] - m0);
                float p2 = exp2f(s[nt][2] - m1);
                float p3 = exp2f(s[nt][3] - m1);
                sum0 += p0 + p1;  sum1 += p2 + p3;
                __nv_bfloat16 h0 = __float2bfloat16_rn(p0), h1b = __float2bfloat16_rn(p1);
                __nv_bfloat16 h2 = __float2bfloat16_rn(p2), h3b = __float2bfloat16_rn(p3);
                float r0 = p0 - __bfloat162float(h0), r1 = p1 - __bfloat162float(h1b);
                float r2 = p2 - __bfloat162float(h2), r3 = p3 - __bfloat162float(h3b);
                int kc = nt >> 1, odd = nt & 1;
                __nv_bfloat162 th01(h0, h1b), th23(h2, h3b);
                aph[kc][odd ? 2 : 0] = *(uint32_t*)&th01;
                aph[kc][odd ? 3 : 1] = *(uint32_t*)&th23;
                apl[kc][odd ? 2 : 0] = packbf(r0, r1);
                apl[kc][odd ? 3 : 1] = packbf(r2, r3);
            }
            sum0 += __shfl_xor_sync(0xffffffffu, sum0, 1);
            sum0 += __shfl_xor_sync(0xffffffffu, sum0, 2);
            sum1 += __shfl_xor_sync(0xffffffffu, sum1, 1);
            sum1 += __shfl_xor_sync(0xffffffffu, sum1, 2);
            l0 = l0 * alpha0 + sum0;
            l1 = l1 * alpha1 + sum1;

            #pragma unroll
            for (int nt = 0; nt < 8; nt++) {
                accO[nt][0] *= alpha0; accO[nt][1] *= alpha0;
                accO[nt][2] *= alpha1; accO[nt][3] *= alpha1;
            }
            // ---- O += P V (3-pass split) ----
            #pragma unroll
            for (int ks = 0; ks < 4; ks++) {
                #pragma unroll
                for (int nt = 0; nt < 8; nt++) {
                    const __nv_bfloat16* p = VTH + (nt*8+g)*GP + ks*16 + t4*2;
                    uint32_t bh0 = *(const uint32_t*)p;
                    uint32_t bh1 = *(const uint32_t*)(p + 8);
                    const __nv_bfloat16* q2 = VTL + (nt*8+g)*GP + ks*16 + t4*2;
                    uint32_t bl0 = *(const uint32_t*)q2;
                    uint32_t bl1 = *(const uint32_t*)(q2 + 8);
                    mma16816(accO[nt], aph[ks], bh0, bh1);
                    mma16816(accO[nt], apl[ks], bh0, bh1);
                    mma16816(accO[nt], aph[ks], bl0, bl1);
                }
            }
        }
        __syncthreads();
    }

    float inv0 = 1.0f / l0, inv1 = 1.0f / l1;
    size_t ob = ((size_t)(b*SEQ) + row0) * EMB + hoff;
    #pragma unroll
    for (int nt = 0; nt < 8; nt++) {
        *(float2*)(ctx + ob + nt*8 + t4*2) =
            make_float2(accO[nt][0]*inv0, accO[nt][1]*inv0);
        *(float2*)(ctx + ob + 8*EMB + nt*8 + t4*2) =
            make_float2(accO[nt][2]*inv1, accO[nt][3]*inv1);
    }
}

// ---------------------------------------------------------------------------
extern "C" void kernel_launch(void* const* d_in, const int* in_sizes, int n_in,
                              void* d_out, int out_size) {
    const float* x  = (const float*)d_in[0];
    const float* Wq = (const float*)d_in[1];
    const float* Wk = (const float*)d_in[2];
    const float* Wv = (const float*)d_in[3];
    const float* Wo = (const float*)d_in[4];
    float* out = (float*)d_out;

    float *qp, *kp, *vp, *cp;
    __nv_bfloat16 *xh, *xl, *ch, *cl, *wh, *wl;
    __nv_bfloat16 *qhp, *qlp, *khp, *klp, *vhp, *vlp;
    cudaGetSymbolAddress((void**)&qp, g_q);
    cudaGetSymbolAddress((void**)&kp, g_k);
    cudaGetSymbolAddress((void**)&vp, g_v);
    cudaGetSymbolAddress((void**)&cp, g_ctx);
    cudaGetSymbolAddress((void**)&xh, g_xh);
    cudaGetSymbolAddress((void**)&xl, g_xl);
    cudaGetSymbolAddress((void**)&ch, g_ch);
    cudaGetSymbolAddress((void**)&cl, g_cl);
    cudaGetSymbolAddress((void**)&wh, g_wh);
    cudaGetSymbolAddress((void**)&wl, g_wl);
    cudaGetSymbolAddress((void**)&qhp, g_qh);
    cudaGetSymbolAddress((void**)&qlp, g_ql);
    cudaGetSymbolAddress((void**)&khp, g_kh);
    cudaGetSymbolAddress((void**)&klp, g_kl);
    cudaGetSymbolAddress((void**)&vhp, g_vh);
    cudaGetSymbolAddress((void**)&vlp, g_vl);

    cudaFuncSetAttribute(gemm_tc, cudaFuncAttributeMaxDynamicSharedMemorySize, GT_SMEM);
    cudaFuncSetAttribute(attn_mma, cudaFuncAttributeMaxDynamicSharedMemorySize, ATTN_SMEM);

    const int NX4 = NROWS * EMB / 4;
    const int NW4 = EMB * EMB / 4;

    split_kernel<<<(NX4 + 255) / 256, 256>>>((const float4*)x,
        (__nv_bfloat162*)xh, (__nv_bfloat162*)xl, NX4);
    const float* Ws[4] = { Wq, Wk, Wv, Wo };
    for (int i = 0; i < 4; i++) {
        split_kernel<<<(NW4 + 255) / 256, 256>>>((const float4*)Ws[i],
            (__nv_bfloat162*)(wh + (size_t)i * EMB * EMB),
            (__nv_bfloat162*)(wl + (size_t)i * EMB * EMB), NW4);
    }

    dim3 ggrid(EMB / 128, NROWS / 128);
    gemm_tc<<<ggrid, 256, GT_SMEM>>>(xh, xl, wh + 0*(size_t)EMB*EMB, wl + 0*(size_t)EMB*EMB, qp);
    gemm_tc<<<ggrid, 256, GT_SMEM>>>(xh, xl, wh + 1*(size_t)EMB*EMB, wl + 1*(size_t)EMB*EMB, kp);
    gemm_tc<<<ggrid, 256, GT_SMEM>>>(xh, xl, wh + 2*(size_t)EMB*EMB, wl + 2*(size_t)EMB*EMB, vp);

    rope_split<<<(BATCH * SEQ * HEADS * 32) / 256, 256>>>(qp, kp, qhp, qlp, khp, klp);
    split_kernel<<<(NX4 + 255) / 256, 256>>>((const float4*)vp,
        (__nv_bfloat162*)vhp, (__nv_bfloat162*)vlp, NX4);

    attn_mma<<<dim3(SEQ / 128, HEADS, BATCH), 256, ATTN_SMEM>>>(qhp, qlp, khp, klp, vhp, vlp, cp);

    split_kernel<<<(NX4 + 255) / 256, 256>>>((const float4*)cp,
        (__nv_bfloat162*)ch, (__nv_bfloat162*)cl, NX4);
    gemm_tc<<<ggrid, 256, GT_SMEM>>>(ch, cl, wh + 3*(size_t)EMB*EMB, wl + 3*(size_t)EMB*EMB, out);
}

// round 8
// speedup vs baseline: 5.5465x; 1.3937x over previous
#include <cuda_runtime.h>
#include <cuda_bf16.h>
#include <cstdint>
#include <math.h>

#define BATCH 2
#define SEQ   2048
#define EMB   1024
#define HEADS 16
#define HDIM  64
#define NROWS (BATCH*SEQ)

// ---------------- scratch (__device__ globals; no allocs allowed) -----------
__device__ __nv_bfloat16 g_xh[NROWS*EMB], g_xl[NROWS*EMB];
__device__ __nv_bfloat16 g_ch[NROWS*EMB], g_cl[NROWS*EMB];
__device__ __nv_bfloat16 g_wh[4][EMB*EMB], g_wl[4][EMB*EMB];
__device__ __nv_bfloat16 g_qh[NROWS*EMB], g_ql[NROWS*EMB];
__device__ __nv_bfloat16 g_kh[NROWS*EMB], g_kl[NROWS*EMB];
__device__ __nv_bfloat16 g_vh[NROWS*EMB], g_vl[NROWS*EMB];

// ---------------- helpers ----------------------------------------------------
__device__ __forceinline__ uint32_t smem_u32(const void* p) {
    uint32_t a;
    asm("{ .reg .u64 t; cvta.to.shared.u64 t, %1; cvt.u32.u64 %0, t; }" : "=r"(a) : "l"(p));
    return a;
}
__device__ __forceinline__ void mma16816(float* c, const uint32_t* a,
                                         uint32_t b0, uint32_t b1) {
    asm volatile(
        "mma.sync.aligned.m16n8k16.row.col.f32.bf16.bf16.f32 "
        "{%0,%1,%2,%3}, {%4,%5,%6,%7}, {%8,%9}, {%0,%1,%2,%3};"
        : "+f"(c[0]), "+f"(c[1]), "+f"(c[2]), "+f"(c[3])
        : "r"(a[0]), "r"(a[1]), "r"(a[2]), "r"(a[3]), "r"(b0), "r"(b1));
}
__device__ __forceinline__ void ldsm4t(uint32_t& r0, uint32_t& r1,
                                       uint32_t& r2, uint32_t& r3, uint32_t addr) {
    asm volatile("ldmatrix.sync.aligned.m8n8.x4.trans.shared.b16 {%0,%1,%2,%3}, [%4];"
        : "=r"(r0), "=r"(r1), "=r"(r2), "=r"(r3) : "r"(addr));
}
__device__ __forceinline__ void cp16(uint32_t dst, const void* src) {
    asm volatile("cp.async.cg.shared.global [%0], [%1], 16;" :: "r"(dst), "l"(src) : "memory");
}
#define CP_COMMIT() asm volatile("cp.async.commit_group;" ::: "memory")
#define CP_WAIT1()  asm volatile("cp.async.wait_group 1;" ::: "memory")
#define CP_WAIT0()  asm volatile("cp.async.wait_group 0;" ::: "memory")

__device__ __forceinline__ uint32_t packbf(float lo, float hi) {
    __nv_bfloat162 t = __floats2bfloat162_rn(lo, hi);
    return *reinterpret_cast<uint32_t*>(&t);
}
__device__ __forceinline__ void store_split(__nv_bfloat16* oh, __nv_bfloat16* ol,
                                            size_t idx, float v0, float v1) {
    __nv_bfloat16 h0 = __float2bfloat16_rn(v0), h1 = __float2bfloat16_rn(v1);
    *(__nv_bfloat162*)(oh + idx) = __nv_bfloat162(h0, h1);
    *(__nv_bfloat162*)(ol + idx) = __nv_bfloat162(
        __float2bfloat16_rn(v0 - __bfloat162float(h0)),
        __float2bfloat16_rn(v1 - __bfloat162float(h1)));
}

// ---------------------------------------------------------------------------
// split fp32 -> bf16 hi + bf16 lo residual (inputs only: x, weights)
// ---------------------------------------------------------------------------
__global__ __launch_bounds__(256) void split_kernel(const float4* __restrict__ in,
                                                    __nv_bfloat162* __restrict__ hi,
                                                    __nv_bfloat162* __restrict__ lo,
                                                    int n4) {
    int i = blockIdx.x * blockDim.x + threadIdx.x;
    if (i >= n4) return;
    float4 a = in[i];
    __nv_bfloat16 h0 = __float2bfloat16_rn(a.x);
    __nv_bfloat16 h1 = __float2bfloat16_rn(a.y);
    __nv_bfloat16 h2 = __float2bfloat16_rn(a.z);
    __nv_bfloat16 h3 = __float2bfloat16_rn(a.w);
    hi[i*2+0] = __nv_bfloat162(h0, h1);
    hi[i*2+1] = __nv_bfloat162(h2, h3);
    lo[i*2+0] = __nv_bfloat162(__float2bfloat16_rn(a.x - __bfloat162float(h0)),
                               __float2bfloat16_rn(a.y - __bfloat162float(h1)));
    lo[i*2+1] = __nv_bfloat162(__float2bfloat16_rn(a.z - __bfloat162float(h2)),
                               __float2bfloat16_rn(a.w - __bfloat162float(h3)));
}

// ---------------------------------------------------------------------------
// GEMM core: 128x128 CTA tile, 8 warps (4m x 2n), warp tile 32x64.
// k-chunk 64, cp.async 2-stage double buffer. bf16 3-pass split.
// ---------------------------------------------------------------------------
#define GP   72
#define GPB  144
#define GT_TILE  (128*GPB)          // 18432 B per tile
#define GT_STAGE (4*GT_TILE)        // 73728 B
#define GT_SMEM  (2*GT_STAGE)       // 147456 B

__device__ __forceinline__ void gemm_core(const __nv_bfloat16* __restrict__ Ah,
                                          const __nv_bfloat16* __restrict__ Al,
                                          const __nv_bfloat16* __restrict__ Bh,
                                          const __nv_bfloat16* __restrict__ Bl,
                                          char* sm, uint32_t smb,
                                          int m0, int n0, float acc[2][8][4]) {
    const int tid = threadIdx.x;
    const int w = tid >> 5, lane = tid & 31, g = lane >> 2, t4 = lane & 3;
    const int wm = w & 3, wn = w >> 2;

    const char* gsrc[4] = { (const char*)(Ah + (size_t)m0 * EMB),
                            (const char*)(Al + (size_t)m0 * EMB),
                            (const char*)(Bh + (size_t)n0 * EMB),
                            (const char*)(Bl + (size_t)n0 * EMB) };

    auto issue = [&](int kc, int stg) {
        uint32_t dstb = smb + stg * GT_STAGE;
        #pragma unroll
        for (int mX = 0; mX < 4; mX++) {
            #pragma unroll
            for (int j = 0; j < 4; j++) {
                int idx = tid + j * 256;
                int r = idx >> 3, c = idx & 7;
                cp16(dstb + mX*GT_TILE + r*GPB + c*16,
                     gsrc[mX] + kc*128 + (size_t)r*2048 + c*16);
            }
        }
        CP_COMMIT();
    };

    issue(0, 0);
    for (int kc = 0; kc < 16; kc++) {
        int cur = kc & 1;
        if (kc < 15) { issue(kc + 1, cur ^ 1); CP_WAIT1(); }
        else         { CP_WAIT0(); }
        __syncthreads();

        char* SAH = sm + cur*GT_STAGE;
        char* SAL = SAH + GT_TILE;
        char* SBH = SAH + 2*GT_TILE;
        char* SBL = SAH + 3*GT_TILE;

        #pragma unroll
        for (int ks = 0; ks < 4; ks++) {
            uint32_t ah[2][4], al[2][4];
            #pragma unroll
            for (int mt = 0; mt < 2; mt++) {
                int row = wm*32 + mt*16 + g;
                const char* p = SAH + row*GPB + ks*32 + t4*4;
                ah[mt][0] = *(const uint32_t*)p;
                ah[mt][1] = *(const uint32_t*)(p + 8*GPB);
                ah[mt][2] = *(const uint32_t*)(p + 16);
                ah[mt][3] = *(const uint32_t*)(p + 8*GPB + 16);
                const char* q = SAL + row*GPB + ks*32 + t4*4;
                al[mt][0] = *(const uint32_t*)q;
                al[mt][1] = *(const uint32_t*)(q + 8*GPB);
                al[mt][2] = *(const uint32_t*)(q + 16);
                al[mt][3] = *(const uint32_t*)(q + 8*GPB + 16);
            }
            #pragma unroll
            for (int nt = 0; nt < 8; nt++) {
                int brow = wn*64 + nt*8 + g;
                const char* p = SBH + brow*GPB + ks*32 + t4*4;
                uint32_t bh0 = *(const uint32_t*)p;
                uint32_t bh1 = *(const uint32_t*)(p + 16);
                const char* q = SBL + brow*GPB + ks*32 + t4*4;
                uint32_t bl0 = *(const uint32_t*)q;
                uint32_t bl1 = *(const uint32_t*)(q + 16);
                mma16816(acc[0][nt], ah[0], bh0, bh1);
                mma16816(acc[1][nt], ah[1], bh0, bh1);
                mma16816(acc[0][nt], al[0], bh0, bh1);
                mma16816(acc[1][nt], al[1], bh0, bh1);
                mma16816(acc[0][nt], ah[0], bl0, bl1);
                mma16816(acc[1][nt], ah[1], bl0, bl1);
            }
        }
        __syncthreads();
    }
}

// ---------------------------------------------------------------------------
// Fused QKV projection: z=0 -> Q (rope+split), z=1 -> K (rope+split),
// z=2 -> V (split). Epilogue writes bf16 hi/lo directly.
// ---------------------------------------------------------------------------
__global__ __launch_bounds__(256) void gemm_qkv(const __nv_bfloat16* __restrict__ xh,
                                                const __nv_bfloat16* __restrict__ xl,
                                                const __nv_bfloat16* __restrict__ wh,
                                                const __nv_bfloat16* __restrict__ wl,
                                                __nv_bfloat16* __restrict__ qh,
                                                __nv_bfloat16* __restrict__ ql,
                                                __nv_bfloat16* __restrict__ kh,
                                                __nv_bfloat16* __restrict__ kl,
                                                __nv_bfloat16* __restrict__ vh,
                                                __nv_bfloat16* __restrict__ vl) {
    extern __shared__ char sm[];
    const int z = blockIdx.z;
    const int n0 = blockIdx.x * 128, m0 = blockIdx.y * 128;
    float acc[2][8][4] = {};
    gemm_core(xh, xl, wh + (size_t)z*EMB*EMB, wl + (size_t)z*EMB*EMB,
              sm, smem_u32(sm), m0, n0, acc);

    const int tid = threadIdx.x;
    const int w = tid >> 5, lane = tid & 31, g = lane >> 2, t4 = lane & 3;
    const int wm = w & 3, wn = w >> 2;

    __nv_bfloat16* oh = (z == 0) ? qh : (z == 1) ? kh : vh;
    __nv_bfloat16* ol = (z == 0) ? ql : (z == 1) ? kl : vl;

    if (z < 2) {
        // RoPE epilogue: warp n-tile (64 cols) == one head; pair (d, d+32) = (nt, nt+4)
        #pragma unroll
        for (int mt = 0; mt < 2; mt++) {
            int rbase = m0 + wm*32 + mt*16 + g;
            #pragma unroll
            for (int jr = 0; jr < 2; jr++) {
                int row = rbase + jr*8;
                int s = row & (SEQ - 1);
                #pragma unroll
                for (int nt = 0; nt < 4; nt++) {
                    int dbase = nt*8 + t4*2;
                    float o0[2], o1[2];
                    #pragma unroll
                    for (int jc = 0; jc < 2; jc++) {
                        int d = dbase + jc;
                        float inv = exp2f(-(float)(2*d) * (13.287712379549449f / 64.0f));
                        float sn, cs;
                        sincosf((float)s * inv, &sn, &cs);
                        float x1 = acc[mt][nt][jr*2+jc];
                        float x2 = acc[mt][nt+4][jr*2+jc];
                        o0[jc] = x1*cs - x2*sn;
                        o1[jc] = x2*cs + x1*sn;
                    }
                    size_t base = (size_t)row * EMB + n0 + wn*64 + dbase;
                    store_split(oh, ol, base,      o0[0], o0[1]);
                    store_split(oh, ol, base + 32, o1[0], o1[1]);
                }
            }
        }
    } else {
        #pragma unroll
        for (int mt = 0; mt < 2; mt++) {
            int row0 = m0 + wm*32 + mt*16 + g;
            #pragma unroll
            for (int nt = 0; nt < 8; nt++) {
                size_t base = (size_t)row0 * EMB + n0 + wn*64 + nt*8 + t4*2;
                store_split(oh, ol, base,          acc[mt][nt][0], acc[mt][nt][1]);
                store_split(oh, ol, base + 8*EMB,  acc[mt][nt][2], acc[mt][nt][3]);
            }
        }
    }
}

// ---------------------------------------------------------------------------
// Output projection: ctx(hi/lo) @ Wo^T -> fp32 out
// ---------------------------------------------------------------------------
__global__ __launch_bounds__(256) void gemm_o(const __nv_bfloat16* __restrict__ Ah,
                                              const __nv_bfloat16* __restrict__ Al,
                                              const __nv_bfloat16* __restrict__ Bh,
                                              const __nv_bfloat16* __restrict__ Bl,
                                              float* __restrict__ C) {
    extern __shared__ char sm[];
    const int n0 = blockIdx.x * 128, m0 = blockIdx.y * 128;
    float acc[2][8][4] = {};
    gemm_core(Ah, Al, Bh, Bl, sm, smem_u32(sm), m0, n0, acc);

    const int tid = threadIdx.x;
    const int w = tid >> 5, lane = tid & 31, g = lane >> 2, t4 = lane & 3;
    const int wm = w & 3, wn = w >> 2;
    #pragma unroll
    for (int mt = 0; mt < 2; mt++) {
        int row = m0 + wm*32 + mt*16 + g;
        #pragma unroll
        for (int nt = 0; nt < 8; nt++) {
            float* p0 = C + (size_t)row * EMB + n0 + wn*64 + nt*8 + t4*2;
            *(float2*)p0 = make_float2(acc[mt][nt][0], acc[mt][nt][1]);
            *(float2*)(p0 + 8*EMB) = make_float2(acc[mt][nt][2], acc[mt][nt][3]);
        }
    }
}

// ---------------------------------------------------------------------------
// mma.sync flash attention, cp.async double-buffered, ldmatrix.trans for V.
// CTA: 128 q-rows x (b,h). 8 warps x 16 rows. Key tiles of 64.
// Stage: KH | KL | VH | VL, each 64 rows x 144B.
// ---------------------------------------------------------------------------
#define AT_TILE  (64*GPB)           // 9216 B
#define AT_STAGE (4*AT_TILE)        // 36864 B
#define ATTN_SMEM (2*AT_STAGE)      // 73728 B

__global__ __launch_bounds__(256) void attn_mma(const __nv_bfloat16* __restrict__ qh,
                                                const __nv_bfloat16* __restrict__ ql,
                                                const __nv_bfloat16* __restrict__ khg,
                                                const __nv_bfloat16* __restrict__ klg,
                                                const __nv_bfloat16* __restrict__ vhg,
                                                const __nv_bfloat16* __restrict__ vlg,
                                                __nv_bfloat16* __restrict__ ch,
                                                __nv_bfloat16* __restrict__ cl) {
    extern __shared__ char sm[];
    const uint32_t smb = smem_u32(sm);

    const int tid = threadIdx.x;
    const int w = tid >> 5, lane = tid & 31, g = lane >> 2, t4 = lane & 3;
    const int qt = blockIdx.x, h = blockIdx.y, b = blockIdx.z;

    const int row_base = qt*128 + w*16;
    const int row0 = row_base + g;
    const int row1 = row0 + 8;
    const size_t hoff = (size_t)h * HDIM;

    // Q fragments (hi/lo)
    uint32_t aqh[4][4], aql[4][4];
    {
        size_t qb = ((size_t)(b*SEQ) + row0) * EMB + hoff;
        #pragma unroll
        for (int ks = 0; ks < 4; ks++) {
            const __nv_bfloat16* p = qh + qb + ks*16 + t4*2;
            aqh[ks][0] = *(const uint32_t*)p;
            aqh[ks][1] = *(const uint32_t*)(p + 8*EMB);
            aqh[ks][2] = *(const uint32_t*)(p + 8);
            aqh[ks][3] = *(const uint32_t*)(p + 8*EMB + 8);
            const __nv_bfloat16* q2 = ql + qb + ks*16 + t4*2;
            aql[ks][0] = *(const uint32_t*)q2;
            aql[ks][1] = *(const uint32_t*)(q2 + 8*EMB);
            aql[ks][2] = *(const uint32_t*)(q2 + 8);
            aql[ks][3] = *(const uint32_t*)(q2 + 8*EMB + 8);
        }
    }

    auto issue = [&](int kt, int stg) {
        size_t kvb = ((size_t)(b*SEQ) + kt*64) * EMB + hoff;
        const char* srcs[4] = { (const char*)(khg + kvb), (const char*)(klg + kvb),
                                (const char*)(vhg + kvb), (const char*)(vlg + kvb) };
        uint32_t dstb = smb + stg * AT_STAGE;
        #pragma unroll
        for (int t = 0; t < 4; t++) {
            #pragma unroll
            for (int j = 0; j < 2; j++) {
                int idx = tid + j*256;
                int r = idx >> 3, c = idx & 7;
                cp16(dstb + t*AT_TILE + r*GPB + c*16, srcs[t] + (size_t)r*2048 + c*16);
            }
        }
        CP_COMMIT();
    };

    float accO[8][4] = {};
    float m0 = -1e30f, m1 = -1e30f, l0 = 0.0f, l1 = 0.0f;
    const float Cs = 0.125f * 1.4426950408889634f;

    const int ntiles = 2*qt + 2;
    const uint32_t vfragoff = (uint32_t)(((lane & 7) + ((lane >> 3) & 1)*8) * GPB + (lane >> 4)*16);

    issue(0, 0);
    for (int kt = 0; kt < ntiles; kt++) {
        int cur = kt & 1;
        if (kt + 1 < ntiles) { issue(kt + 1, cur ^ 1); CP_WAIT1(); }
        else                 { CP_WAIT0(); }
        __syncthreads();

        char* KH = sm + cur*AT_STAGE;
        char* KL = KH + AT_TILE;
        const uint32_t vhb = smb + cur*AT_STAGE + 2*AT_TILE + vfragoff;
        const uint32_t vlb = vhb + AT_TILE;

        if (kt*64 <= row_base + 15) {
            // ---- S = Q K^T (3-pass split) ----
            float s[8][4] = {};
            #pragma unroll
            for (int ks = 0; ks < 4; ks++) {
                #pragma unroll
                for (int nt = 0; nt < 8; nt++) {
                    const char* p = KH + (nt*8+g)*GPB + ks*32 + t4*4;
                    uint32_t bh0 = *(const uint32_t*)p;
                    uint32_t bh1 = *(const uint32_t*)(p + 16);
                    const char* q2 = KL + (nt*8+g)*GPB + ks*32 + t4*4;
                    uint32_t bl0 = *(const uint32_t*)q2;
                    uint32_t bl1 = *(const uint32_t*)(q2 + 16);
                    mma16816(s[nt], aqh[ks], bh0, bh1);
                    mma16816(s[nt], aql[ks], bh0, bh1);
                    mma16816(s[nt], aqh[ks], bl0, bl1);
                }
            }
            // ---- mask + scale ----
            #pragma unroll
            for (int nt = 0; nt < 8; nt++) {
                int colb = kt*64 + nt*8 + t4*2;
                s[nt][0] = (colb     > row0) ? -3e28f : s[nt][0]*Cs;
                s[nt][1] = (colb + 1 > row0) ? -3e28f : s[nt][1]*Cs;
                s[nt][2] = (colb     > row1) ? -3e28f : s[nt][2]*Cs;
                s[nt][3] = (colb + 1 > row1) ? -3e28f : s[nt][3]*Cs;
            }
            // ---- row max ----
            float rm0 = -3e28f, rm1 = -3e28f;
            #pragma unroll
            for (int nt = 0; nt < 8; nt++) {
                rm0 = fmaxf(rm0, fmaxf(s[nt][0], s[nt][1]));
                rm1 = fmaxf(rm1, fmaxf(s[nt][2], s[nt][3]));
            }
            rm0 = fmaxf(rm0, __shfl_xor_sync(0xffffffffu, rm0, 1));
            rm0 = fmaxf(rm0, __shfl_xor_sync(0xffffffffu, rm0, 2));
            rm1 = fmaxf(rm1, __shfl_xor_sync(0xffffffffu, rm1, 1));
            rm1 = fmaxf(rm1, __shfl_xor_sync(0xffffffffu, rm1, 2));

            float mn0 = fmaxf(m0, rm0), mn1 = fmaxf(m1, rm1);
            float alpha0 = exp2f(m0 - mn0), alpha1 = exp2f(m1 - mn1);
            m0 = mn0; m1 = mn1;

            // ---- p = exp2(s - m), pack to hi/lo A-fragments ----
            float sum0 = 0.0f, sum1 = 0.0f;
            uint32_t aph[4][4], apl[4][4];
            #pragma unroll
            for (int nt = 0; nt < 8; nt++) {
                float p0 = exp2f(s[nt][0] - m0);
                float p1 = exp2f(s[nt][1] - m0);
                float p2 = exp2f(s[nt][2] - m1);
                float p3 = exp2f(s[nt][3] - m1);
                sum0 += p0 + p1;  sum1 += p2 + p3;
                __nv_bfloat16 h0 = __float2bfloat16_rn(p0), h1b = __float2bfloat16_rn(p1);
                __nv_bfloat16 h2 = __float2bfloat16_rn(p2), h3b = __float2bfloat16_rn(p3);
                float r0 = p0 - __bfloat162float(h0), r1 = p1 - __bfloat162float(h1b);
                float r2 = p2 - __bfloat162float(h2), r3 = p3 - __bfloat162float(h3b);
                int kc = nt >> 1, odd = nt & 1;
                __nv_bfloat162 th01(h0, h1b), th23(h2, h3b);
                aph[kc][odd ? 2 : 0] = *(uint32_t*)&th01;
                aph[kc][odd ? 3 : 1] = *(uint32_t*)&th23;
                apl[kc][odd ? 2 : 0] = packbf(r0, r1);
                apl[kc][odd ? 3 : 1] = packbf(r2, r3);
            }
            sum0 += __shfl_xor_sync(0xffffffffu, sum0, 1);
            sum0 += __shfl_xor_sync(0xffffffffu, sum0, 2);
            sum1 += __shfl_xor_sync(0xffffffffu, sum1, 1);
            sum1 += __shfl_xor_sync(0xffffffffu, sum1, 2);
            l0 = l0 * alpha0 + sum0;
            l1 = l1 * alpha1 + sum1;

            #pragma unroll
            for (int nt = 0; nt < 8; nt++) {
                accO[nt][0] *= alpha0; accO[nt][1] *= alpha0;
                accO[nt][2] *= alpha1; accO[nt][3] *= alpha1;
            }
            // ---- O += P V (3-pass split), V via ldmatrix.trans ----
            #pragma unroll
            for (int ks = 0; ks < 4; ks++) {
                #pragma unroll
                for (int ntp = 0; ntp < 4; ntp++) {
                    uint32_t r0, r1, r2, r3;
                    ldsm4t(r0, r1, r2, r3, vhb + ks*16*GPB + ntp*32);
                    mma16816(accO[2*ntp],   aph[ks], r0, r1);
                    mma16816(accO[2*ntp+1], aph[ks], r2, r3);
                    mma16816(accO[2*ntp],   apl[ks], r0, r1);
                    mma16816(accO[2*ntp+1], apl[ks], r2, r3);
                    ldsm4t(r0, r1, r2, r3, vlb + ks*16*GPB + ntp*32);
                    mma16816(accO[2*ntp],   aph[ks], r0, r1);
                    mma16816(accO[2*ntp+1], aph[ks], r2, r3);
                }
            }
        }
        __syncthreads();
    }

    float inv0 = 1.0f / l0, inv1 = 1.0f / l1;
    size_t ob = ((size_t)(b*SEQ) + row0) * EMB + hoff;
    #pragma unroll
    for (int nt = 0; nt < 8; nt++) {
        store_split(ch, cl, ob + nt*8 + t4*2,          accO[nt][0]*inv0, accO[nt][1]*inv0);
        store_split(ch, cl, ob + 8*EMB + nt*8 + t4*2,  accO[nt][2]*inv1, accO[nt][3]*inv1);
    }
}

// ---------------------------------------------------------------------------
extern "C" void kernel_launch(void* const* d_in, const int* in_sizes, int n_in,
                              void* d_out, int out_size) {
    const float* x  = (const float*)d_in[0];
    const float* Wq = (const float*)d_in[1];
    const float* Wk = (const float*)d_in[2];
    const float* Wv = (const float*)d_in[3];
    const float* Wo = (const float*)d_in[4];
    float* out = (float*)d_out;

    __nv_bfloat16 *xh, *xl, *ch, *cl, *wh, *wl;
    __nv_bfloat16 *qhp, *qlp, *khp, *klp, *vhp, *vlp;
    cudaGetSymbolAddress((void**)&xh, g_xh);
    cudaGetSymbolAddress((void**)&xl, g_xl);
    cudaGetSymbolAddress((void**)&ch, g_ch);
    cudaGetSymbolAddress((void**)&cl, g_cl);
    cudaGetSymbolAddress((void**)&wh, g_wh);
    cudaGetSymbolAddress((void**)&wl, g_wl);
    cudaGetSymbolAddress((void**)&qhp, g_qh);
    cudaGetSymbolAddress((void**)&qlp, g_ql);
    cudaGetSymbolAddress((void**)&khp, g_kh);
    cudaGetSymbolAddress((void**)&klp, g_kl);
    cudaGetSymbolAddress((void**)&vhp, g_vh);
    cudaGetSymbolAddress((void**)&vlp, g_vl);

    cudaFuncSetAttribute(gemm_qkv, cudaFuncAttributeMaxDynamicSharedMemorySize, GT_SMEM);
    cudaFuncSetAttribute(gemm_o,   cudaFuncAttributeMaxDynamicSharedMemorySize, GT_SMEM);
    cudaFuncSetAttribute(attn_mma, cudaFuncAttributeMaxDynamicSharedMemorySize, ATTN_SMEM);

    const int NX4 = NROWS * EMB / 4;
    const int NW4 = EMB * EMB / 4;

    split_kernel<<<(NX4 + 255) / 256, 256>>>((const float4*)x,
        (__nv_bfloat162*)xh, (__nv_bfloat162*)xl, NX4);
    const float* Ws[4] = { Wq, Wk, Wv, Wo };
    for (int i = 0; i < 4; i++) {
        split_kernel<<<(NW4 + 255) / 256, 256>>>((const float4*)Ws[i],
            (__nv_bfloat162*)(wh + (size_t)i * EMB * EMB),
            (__nv_bfloat162*)(wl + (size_t)i * EMB * EMB), NW4);
    }

    gemm_qkv<<<dim3(EMB/128, NROWS/128, 3), 256, GT_SMEM>>>(
        xh, xl, wh, wl, qhp, qlp, khp, klp, vhp, vlp);

    attn_mma<<<dim3(SEQ/128, HEADS, BATCH), 256, ATTN_SMEM>>>(
        qhp, qlp, khp, klp, vhp, vlp, ch, cl);

    gemm_o<<<dim3(EMB/128, NROWS/128), 256, GT_SMEM>>>(
        ch, cl, wh + 3*(size_t)EMB*EMB, wl + 3*(size_t)EMB*EMB, out);
}